// round 7
// baseline (speedup 1.0000x reference)
#include <cuda_runtime.h>
#include <cuda_bf16.h>
#include <math.h>

#define Bsz 512
#define Hd  1024
#define Od  512
#define KC  1536   // Od + Hd
#define G4  4096   // 4*Hd
#define KSPLIT 8

// ---------------- scratch ----------------
__device__ __nv_bfloat16 g_Xh[2][Bsz * KC];   // ping-pong [buf][B][KC]
__device__ __nv_bfloat16 g_Xl[2][Bsz * KC];
__device__ __nv_bfloat16 g_Wh[G4 * KC];       // gate-interleaved [4j+gate][k]
__device__ __nv_bfloat16 g_Wl[G4 * KC];
__device__ __nv_bfloat16 g_Woh[Od * Hd];
__device__ __nv_bfloat16 g_Wol[Od * Hd];
__device__ float g_c[Bsz * Hd];               // [b][j]
__device__ float g_bias[G4];                  // gate-interleaved
__device__ float g_gacc[2][Bsz * G4];         // gates h-part partials
__device__ float g_lp[KSPLIT][Bsz * Od];      // logits split-K partials

__device__ __forceinline__ void split_bf16(float v, __nv_bfloat16& hi, __nv_bfloat16& lo) {
    hi = __float2bfloat16(v);
    lo = __float2bfloat16(v - __bfloat162float(hi));
}
__device__ __forceinline__ float sigm(float x) { return 1.0f / (1.0f + __expf(-x)); }
__device__ __forceinline__ float ftanh(float x) { return 1.0f - 2.0f / (__expf(2.0f * x) + 1.0f); }

// ---------------- prep -------------------
__global__ void prep_weights(const float* __restrict__ W_ih,
                             const float* __restrict__ W_hh,
                             const float* __restrict__ b_ih,
                             const float* __restrict__ b_hh,
                             const float* __restrict__ W_out) {
    int idx = blockIdx.x * blockDim.x + threadIdx.x;
    if (idx < G4 * KC) {
        int r = idx / KC;
        int k = idx - r * KC;
        int j = r >> 2, gate = r & 3;
        int orow = gate * Hd + j;
        float w = (k < Od) ? W_ih[orow * Od + k] : W_hh[orow * Hd + (k - Od)];
        __nv_bfloat16 hi, lo;
        split_bf16(w, hi, lo);
        g_Wh[idx] = hi;
        g_Wl[idx] = lo;
    }
    if (idx < G4) {
        int j = idx >> 2, gate = idx & 3;
        g_bias[idx] = b_ih[gate * Hd + j] + b_hh[gate * Hd + j];
    }
    if (idx < Od * Hd) {
        __nv_bfloat16 hi, lo;
        split_bf16(W_out[idx], hi, lo);
        g_Woh[idx] = hi;
        g_Wol[idx] = lo;
    }
}

__global__ void prep_state(const float* __restrict__ h0,
                           const float* __restrict__ c0) {
    int idx = blockIdx.x * blockDim.x + threadIdx.x;
    if (idx < Bsz * Hd) {
        int b = idx >> 10;
        int j = idx & (Hd - 1);
        __nv_bfloat16 hi, lo;
        split_bf16(h0[idx], hi, lo);
        g_Xh[0][b * KC + Od + j] = hi;
        g_Xl[0][b * KC + Od + j] = lo;
        g_c[idx] = c0[idx];
    }
    if (idx < Bsz * Od) {
        int b = idx >> 9;
        int k = idx & (Od - 1);
        g_Xh[0][b * KC + k] = __float2bfloat16(0.0f);
        g_Xl[0][b * KC + k] = __float2bfloat16(0.0f);
    }
}

// ---------------- asm helpers --------------------------------------------
#define SWZ(b) ((b) ^ (((b) >> 3) & 0x30))   // 64B-row XOR swizzle

#define CP_ASYNC16(dst, src) asm volatile("cp.async.cg.shared.global [%0], [%1], 16;\n" :: "r"(dst), "l"(src))
#define CP_COMMIT            asm volatile("cp.async.commit_group;\n")
#define CP_WAIT2             asm volatile("cp.async.wait_group 2;\n")
#define CP_WAIT1             asm volatile("cp.async.wait_group 1;\n")
#define CP_WAIT0             asm volatile("cp.async.wait_group 0;\n")

#define LDSM_X4(d0, d1, d2, d3, addr) \
    asm volatile("ldmatrix.sync.aligned.m8n8.x4.shared.b16 {%0,%1,%2,%3}, [%4];" \
                 : "=r"(d0), "=r"(d1), "=r"(d2), "=r"(d3) : "r"(addr))

#define MMA_BF16(acc, a, b) \
    asm volatile( \
        "mma.sync.aligned.m16n8k16.row.col.f32.bf16.bf16.f32 " \
        "{%0,%1,%2,%3}, {%4,%5,%6,%7}, {%8,%9}, {%0,%1,%2,%3};" \
        : "+f"((acc)[0]), "+f"((acc)[1]), "+f"((acc)[2]), "+f"((acc)[3]) \
        : "r"((a)[0]), "r"((a)[1]), "r"((a)[2]), "r"((a)[3]), \
          "r"((b)[0]), "r"((b)[1]))

#define STAGE_B 32768                 // Ah 8K | Al 8K | Bh 8K | Bl 8K
#define SMEM_B  (3 * STAGE_B)         // 96 KB, 3-stage

// ==========================================================================
// shared GEMM body: 128x128 tile, BK=32, 3 bf16-split products, fp32 acc.
// 8 warps (2x4), warp tile 64x32. A rows from (Ah,Al), B rows from (Bh,Bl).
// ==========================================================================
__device__ __forceinline__ void gemm128_body(
    unsigned sbase, int tid,
    const __nv_bfloat16* __restrict__ Ah, const __nv_bfloat16* __restrict__ Al,
    size_t strideA, int aoff,
    const __nv_bfloat16* __restrict__ Bh, const __nv_bfloat16* __restrict__ Bl,
    size_t strideB, int boff,
    int bm, int bn, int k0base, int nt,
    float (&acc)[4][4][4])
{
    const int wid  = tid >> 5;
    const int lane = tid & 31;
    const int warp_m = wid >> 2;
    const int warp_n = wid & 3;

    const int rA0 = tid >> 2;        // 0..63
    const int rA1 = rA0 + 64;
    const int kc  = tid & 3;
    const unsigned sOff0 = SWZ((unsigned)(rA0 * 64 + kc * 16));
    const unsigned sOff1 = SWZ((unsigned)(rA1 * 64 + kc * 16));

    auto load = [&](int I, int BUF) {
        int k0 = k0base + I * 32 + kc * 8;
        unsigned s = sbase + BUF * STAGE_B;
        size_t a0 = (size_t)(bm + rA0) * strideA + aoff + k0;
        size_t a1 = (size_t)(bm + rA1) * strideA + aoff + k0;
        size_t b0 = (size_t)(bn + rA0) * strideB + boff + k0;
        size_t b1 = (size_t)(bn + rA1) * strideB + boff + k0;
        CP_ASYNC16(s + sOff0,          Ah + a0);
        CP_ASYNC16(s + sOff1,          Ah + a1);
        CP_ASYNC16(s + 8192  + sOff0,  Al + a0);
        CP_ASYNC16(s + 8192  + sOff1,  Al + a1);
        CP_ASYNC16(s + 16384 + sOff0,  Bh + b0);
        CP_ASYNC16(s + 16384 + sOff1,  Bh + b1);
        CP_ASYNC16(s + 24576 + sOff0,  Bl + b0);
        CP_ASYNC16(s + 24576 + sOff1,  Bl + b1);
        CP_COMMIT;
    };

    load(0, 0);
    load(1, 1);

    for (int it = 0; it < nt; it++) {
        const int buf = it % 3;
        if (it + 2 < nt) {
            load(it + 2, (it + 2) % 3);
            CP_WAIT2;
        } else if (it + 1 < nt) {
            CP_WAIT1;
        } else {
            CP_WAIT0;
        }
        __syncthreads();

        const unsigned sb = sbase + buf * STAGE_B;

        #pragma unroll
        for (int kk = 0; kk < 2; kk++) {
            const unsigned ar  = (unsigned)(lane & 15);
            const unsigned ahk = (unsigned)(lane >> 4);
            unsigned ah[4][4], al[4][4];
            #pragma unroll
            for (int mf = 0; mf < 4; mf++) {
                unsigned byte = (warp_m * 64 + mf * 16 + ar) * 64 + kk * 32 + ahk * 16;
                unsigned sw = SWZ(byte);
                LDSM_X4(ah[mf][0], ah[mf][1], ah[mf][2], ah[mf][3], sb + sw);
                LDSM_X4(al[mf][0], al[mf][1], al[mf][2], al[mf][3], sb + 8192 + sw);
            }
            unsigned bh[4][2], bl[4][2];
            #pragma unroll
            for (int pr = 0; pr < 2; pr++) {
                unsigned n = warp_n * 32 + pr * 16 + (lane & 7) + ((lane >> 4) & 1) * 8;
                unsigned byte = n * 64 + kk * 32 + ((lane >> 3) & 1) * 16;
                unsigned sw = SWZ(byte);
                unsigned r0, r1, r2, r3;
                LDSM_X4(r0, r1, r2, r3, sb + 16384 + sw);
                bh[2 * pr][0] = r0;      bh[2 * pr][1] = r1;
                bh[2 * pr + 1][0] = r2;  bh[2 * pr + 1][1] = r3;
                LDSM_X4(r0, r1, r2, r3, sb + 24576 + sw);
                bl[2 * pr][0] = r0;      bl[2 * pr][1] = r1;
                bl[2 * pr + 1][0] = r2;  bl[2 * pr + 1][1] = r3;
            }
            #pragma unroll
            for (int mf = 0; mf < 4; mf++)
                #pragma unroll
                for (int nf = 0; nf < 4; nf++)
                    MMA_BF16(acc[mf][nf], ah[mf], bh[nf]);
            #pragma unroll
            for (int mf = 0; mf < 4; mf++)
                #pragma unroll
                for (int nf = 0; nf < 4; nf++)
                    MMA_BF16(acc[mf][nf], ah[mf], bl[nf]);
            #pragma unroll
            for (int mf = 0; mf < 4; mf++)
                #pragma unroll
                for (int nf = 0; nf < 4; nf++)
                    MMA_BF16(acc[mf][nf], al[mf], bh[nf]);
        }
        __syncthreads();
    }
}

// ==========================================================================
// gates_x: x-part GEMM (K=512) + gacc partial add + fused LSTM cell epilogue
// grid (32, 4) = 128 blocks.
// ==========================================================================
__global__ __launch_bounds__(256) void gates_x(int rd, int wr) {
    extern __shared__ __align__(1024) unsigned char smg[];
    const unsigned sbase = (unsigned)__cvta_generic_to_shared(smg);

    const int tid  = threadIdx.x;
    const int wid  = tid >> 5;
    const int lane = tid & 31;
    const int warp_m = wid >> 2;
    const int warp_n = wid & 3;
    const int bm = blockIdx.y * 128;
    const int bn = blockIdx.x * 128;

    float acc[4][4][4];
    #pragma unroll
    for (int i = 0; i < 4; i++)
        #pragma unroll
        for (int j = 0; j < 4; j++)
            #pragma unroll
            for (int q = 0; q < 4; q++) acc[i][j][q] = 0.0f;

    gemm128_body(sbase, tid, g_Xh[rd], g_Xl[rd], KC, 0,
                 g_Wh, g_Wl, KC, 0, bm, bn, 0, Od / 32, acc);

    const float* gacc = g_gacc[rd];
    __nv_bfloat16* Xh_w = g_Xh[wr];
    __nv_bfloat16* Xl_w = g_Xl[wr];
    const bool odd = lane & 1;

    #pragma unroll
    for (int mf = 0; mf < 4; mf++) {
        #pragma unroll
        for (int nf = 0; nf < 4; nf++) {
            int rowbase = bm + warp_m * 64 + mf * 16 + (lane >> 2);
            int colbase = bn + warp_n * 32 + nf * 8 + (lane & 3) * 2;
            int j = colbase >> 2;

            float2 ga0 = *(const float2*)&gacc[(size_t)rowbase * G4 + colbase];
            float2 ga1 = *(const float2*)&gacc[(size_t)(rowbase + 8) * G4 + colbase];
            acc[mf][nf][0] += ga0.x;
            acc[mf][nf][1] += ga0.y;
            acc[mf][nf][2] += ga1.x;
            acc[mf][nf][3] += ga1.y;

            float p0 = __shfl_xor_sync(0xffffffffu, acc[mf][nf][0], 1);
            float p1 = __shfl_xor_sync(0xffffffffu, acc[mf][nf][1], 1);
            float p2 = __shfl_xor_sync(0xffffffffu, acc[mf][nf][2], 1);
            float p3 = __shfl_xor_sync(0xffffffffu, acc[mf][nf][3], 1);

            float gi, gf, gg, go;
            int r;
            if (!odd) { gi = acc[mf][nf][0]; gf = acc[mf][nf][1]; gg = p0; go = p1; r = rowbase; }
            else      { gi = p2;             gf = p3;             gg = acc[mf][nf][2]; go = acc[mf][nf][3]; r = rowbase + 8; }

            float4 bs = *(const float4*)&g_bias[j * 4];
            gi += bs.x; gf += bs.y; gg += bs.z; go += bs.w;

            float c  = g_c[r * Hd + j];
            float cn = sigm(gf) * c + sigm(gi) * ftanh(gg);
            g_c[r * Hd + j] = cn;
            float hn = sigm(go) * ftanh(cn);

            __nv_bfloat16 hi, lo;
            split_bf16(hn, hi, lo);
            Xh_w[r * KC + Od + j] = hi;
            Xl_w[r * KC + Od + j] = lo;
        }
    }
}

// ==========================================================================
// hwork: ONE launch, two roles co-scheduled (no streams needed):
//   blocks [0,128)   : gates h-part (K=1024) -> g_gacc[gb]   (next step)
//   blocks [128,256) : logits split-K=8      -> g_lp[kz]     (this step)
// ==========================================================================
__global__ __launch_bounds__(256, 2) void hwork(int xb, int gb, int do_logits, int do_h) {
    extern __shared__ __align__(1024) unsigned char smg[];
    const unsigned sbase = (unsigned)__cvta_generic_to_shared(smg);

    const int tid  = threadIdx.x;
    const int wid  = tid >> 5;
    const int lane = tid & 31;
    const int warp_m = wid >> 2;
    const int warp_n = wid & 3;

    float acc[4][4][4];
    #pragma unroll
    for (int i = 0; i < 4; i++)
        #pragma unroll
        for (int j = 0; j < 4; j++)
            #pragma unroll
            for (int q = 0; q < 4; q++) acc[i][j][q] = 0.0f;

    if (blockIdx.x < 128) {
        if (!do_h) return;
        const int bm = (blockIdx.x & 3) * 128;
        const int bn = (blockIdx.x >> 2) * 128;

        gemm128_body(sbase, tid, g_Xh[xb], g_Xl[xb], KC, Od,
                     g_Wh, g_Wl, KC, Od, bm, bn, 0, Hd / 32, acc);

        float* gacc = g_gacc[gb];
        #pragma unroll
        for (int mf = 0; mf < 4; mf++) {
            #pragma unroll
            for (int nf = 0; nf < 4; nf++) {
                int row = bm + warp_m * 64 + mf * 16 + (lane >> 2);
                int col = bn + warp_n * 32 + nf * 8 + (lane & 3) * 2;
                *(float2*)&gacc[(size_t)row * G4 + col] = make_float2(acc[mf][nf][0], acc[mf][nf][1]);
                *(float2*)&gacc[(size_t)(row + 8) * G4 + col] = make_float2(acc[mf][nf][2], acc[mf][nf][3]);
            }
        }
    } else {
        if (!do_logits) return;
        const int id = blockIdx.x - 128;          // 0..127
        const int kz = id >> 4;                   // 0..7
        const int bm = ((id >> 2) & 3) * 128;
        const int bn = (id & 3) * 128;

        gemm128_body(sbase, tid, g_Xh[xb], g_Xl[xb], KC, Od,
                     g_Woh, g_Wol, Hd, 0, bm, bn, kz * (Hd / KSPLIT), (Hd / KSPLIT) / 32, acc);

        float* lp = g_lp[kz];
        #pragma unroll
        for (int mf = 0; mf < 4; mf++) {
            #pragma unroll
            for (int nf = 0; nf < 4; nf++) {
                int row = bm + warp_m * 64 + mf * 16 + (lane >> 2);
                int col = bn + warp_n * 32 + nf * 8 + (lane & 3) * 2;
                *(float2*)&lp[(size_t)row * Od + col] = make_float2(acc[mf][nf][0], acc[mf][nf][1]);
                *(float2*)&lp[(size_t)(row + 8) * Od + col] = make_float2(acc[mf][nf][2], acc[mf][nf][3]);
            }
        }
    }
}

// ==========================================================================
// softmax + feedback (sums KSPLIT partials)
// ==========================================================================
#define RB 4

__global__ __launch_bounds__(256) void softmax_fb(const float* __restrict__ b_out,
                                                  float* __restrict__ out,
                                                  int step_off, int wr) {
    __shared__ float red[RB][8];

    const int b0 = blockIdx.x * RB;
    const int tid = threadIdx.x;
    const int warp = tid >> 5, lane = tid & 31;

    const int c0 = tid;
    const int c1 = tid + 256;
    const float bo0 = b_out[c0];
    const float bo1 = b_out[c1];

    float acc0[RB], acc1[RB];
    #pragma unroll
    for (int r = 0; r < RB; r++) {
        size_t i0 = (size_t)(b0 + r) * Od + c0;
        size_t i1 = (size_t)(b0 + r) * Od + c1;
        float s0 = bo0, s1 = bo1;
        #pragma unroll
        for (int z = 0; z < KSPLIT; z++) {
            s0 += g_lp[z][i0];
            s1 += g_lp[z][i1];
        }
        acc0[r] = s0;
        acc1[r] = s1;
    }

    #pragma unroll
    for (int r = 0; r < RB; r++) {
        float mm = fmaxf(acc0[r], acc1[r]);
        #pragma unroll
        for (int o = 16; o; o >>= 1) mm = fmaxf(mm, __shfl_xor_sync(0xffffffffu, mm, o));
        if (lane == 0) red[r][warp] = mm;
    }
    __syncthreads();
    float m[RB];
    #pragma unroll
    for (int r = 0; r < RB; r++) {
        float mm = red[r][0];
        #pragma unroll
        for (int w = 1; w < 8; w++) mm = fmaxf(mm, red[r][w]);
        m[r] = mm;
    }
    __syncthreads();

    #pragma unroll
    for (int r = 0; r < RB; r++) {
        acc0[r] = __expf(acc0[r] - m[r]);
        acc1[r] = __expf(acc1[r] - m[r]);
        float ss = acc0[r] + acc1[r];
        #pragma unroll
        for (int o = 16; o; o >>= 1) ss += __shfl_xor_sync(0xffffffffu, ss, o);
        if (lane == 0) red[r][warp] = ss;
    }
    __syncthreads();

    __nv_bfloat16* Xh_w = g_Xh[wr];
    __nv_bfloat16* Xl_w = g_Xl[wr];

    #pragma unroll
    for (int r = 0; r < RB; r++) {
        float ss = 0.0f;
        #pragma unroll
        for (int w = 0; w < 8; w++) ss += red[r][w];
        float inv = 1.0f / ss;
        float y0 = acc0[r] * inv;
        float y1 = acc1[r] * inv;
        int b = b0 + r;
        out[step_off + b * Od + c0] = y0;
        out[step_off + b * Od + c1] = y1;
        __nv_bfloat16 hi, lo;
        split_bf16(y0, hi, lo);
        Xh_w[b * KC + c0] = hi;  Xl_w[b * KC + c0] = lo;
        split_bf16(y1, hi, lo);
        Xh_w[b * KC + c1] = hi;  Xl_w[b * KC + c1] = lo;
    }
}

// ---------------- launcher ------------------------------------------------
extern "C" void kernel_launch(void* const* d_in, const int* in_sizes, int n_in,
                              void* d_out, int out_size) {
    const float* h0    = (const float*)d_in[0];
    const float* c0    = (const float*)d_in[1];
    const float* W_ih  = (const float*)d_in[2];
    const float* W_hh  = (const float*)d_in[3];
    const float* b_ih  = (const float*)d_in[4];
    const float* b_hh  = (const float*)d_in[5];
    const float* W_out = (const float*)d_in[6];
    const float* b_out = (const float*)d_in[7];
    float* out = (float*)d_out;

    const int T = out_size / (Bsz * Od);

    cudaFuncSetAttribute(gates_x, cudaFuncAttributeMaxDynamicSharedMemorySize, SMEM_B);
    cudaFuncSetAttribute(hwork,   cudaFuncAttributeMaxDynamicSharedMemorySize, SMEM_B);

    prep_weights<<<(G4 * KC + 255) / 256, 256>>>(W_ih, W_hh, b_ih, b_hh, W_out);
    prep_state<<<(Bsz * Hd + 255) / 256, 256>>>(h0, c0);

    // step-0 h-part: gacc[0] from h0 (in X[0]); logits role disabled
    hwork<<<256, 256, SMEM_B>>>(0, 0, 0, 1);

    dim3 xgrid(G4 / 128, Bsz / 128);   // (32, 4) = 128 blocks
    for (int t = 0; t < T; t++) {
        int rd = t & 1, wr = rd ^ 1;
        // x-part + cell update: reads X[rd] x-cols + gacc[rd]; writes h into X[wr]
        gates_x<<<xgrid, 256, SMEM_B>>>(rd, wr);
        // logits(t) from X[wr] h-cols  +  gates h-part for step t+1 -> gacc[wr]
        hwork<<<256, 256, SMEM_B>>>(wr, wr, 1, (t + 1 < T) ? 1 : 0);
        // softmax + feedback: writes out + X[wr] x-cols
        softmax_fb<<<Bsz / RB, 256>>>(b_out, out, (T - 1 - t) * Bsz * Od, wr);
    }
}